// round 6
// baseline (speedup 1.0000x reference)
#include <cuda_runtime.h>
#include <math.h>

#define NW 22
#define NBLK 296   // 2 blocks per SM on 148 SMs — all SMs active, balanced

// R6: grid-stride over 1024 output tiles (1024 float4 each), 296x1024 launch.
// Math (validated R2-R5):
//   out[4b+2i+j] = |TA[(b>>9)&1023] * TB[b&1023]| * S[c19,c0,c1,i,j]
//   b = (T<<10) + t for tile T, thread t:
//     TB index = t                (tile-invariant)
//     TA index = ((T<<1)|(t>>9)) & 1023   (warp-uniform)
//     S index bits: c19=t&1, c0=(T>>9)&1, c1=(T>>8)&1

__global__ void __launch_bounds__(1024) qk_fused(const float* __restrict__ x,
                                                 const float* __restrict__ y,
                                                 float4* __restrict__ out) {
    __shared__ float cx[NW], sx[NW], cy[NW], sy[NW];
    __shared__ float pc[NW], ps[NW];
    __shared__ float sTA[1024], sTB[1024];
    __shared__ float4 sS[8];
    const int t = threadIdx.x;

    if (t < NW) {
        float sxx, cxx, syy, cyy;
        __sincosf(0.5f * x[t], &sxx, &cxx);
        __sincosf(0.5f * y[t], &syy, &cyy);
        cx[t] = cxx; sx[t] = sxx; cy[t] = cyy; sy[t] = syy;
        pc[t] = cxx * cyy; ps[t] = sxx * syy;
    }
    __syncthreads();

    // One TA and one TB entry per thread.
    {
        int u = t ^ (t >> 1);
        float a = 1.0f, bb = 1.0f;
        #pragma unroll
        for (int j = 0; j < 9; ++j) {
            bool bit = (u >> j) & 1;
            a  *= bit ? ps[10 - j] : pc[10 - j];   // wires 2..10
            bb *= bit ? ps[19 - j] : pc[19 - j];   // wires 11..19
        }
        sTA[t] = a;
        sTB[t] = bb;
    }

    // S table: pre-contracted 2x2 matmul tail + abs (32 scalars, all >= 0).
    if (t < 32) {
        int j   =  t        & 1;
        int i   = (t >> 1)  & 1;
        int c1  = (t >> 2)  & 1;
        int c0  = (t >> 3)  & 1;
        int c19 = (t >> 4)  & 1;
        float s = 0.0f;
        #pragma unroll
        for (int k = 0; k < 2; ++k) {
            float ty = ((c19 ^ i)     ? sy[20] : cy[20])
                     * ((i   ^ k)     ? sy[21] : cy[21])
                     * ((c0  ^ k)     ? sy[0]  : cy[0])
                     * ((c0 ^ c1 ^ k) ? sy[1]  : cy[1]);
            float tx = ((c19 ^ k)     ? sx[20] : cx[20])
                     * ((k   ^ j)     ? sx[21] : cx[21])
                     * ((c0  ^ j)     ? sx[0]  : cx[0])
                     * ((c0 ^ c1 ^ j) ? sx[1]  : cx[1]);
            s += ty * tx;
        }
        reinterpret_cast<float*>(sS)[t] = fabsf(s);
    }
    __syncthreads();

    const float B = sTB[t];
    const unsigned c19bit = ((unsigned)t & 1u) << 2;

    // Grid-stride over the 1024 tiles.
    for (unsigned T = blockIdx.x; T < 1024u; T += NBLK) {
        unsigned b = (T << 10) + (unsigned)t;
        float A = sTA[(b >> 9) & 1023u];                       // warp-uniform LDS
        float m = fabsf(A * B);
        float4 s = sS[c19bit | (((T >> 9) & 1u) << 1) | ((T >> 8) & 1u)];
        float4 o;
        o.x = m * s.x; o.y = m * s.y; o.z = m * s.z; o.w = m * s.w;
        out[b] = o;                                            // STG.128, coalesced
    }
}

extern "C" void kernel_launch(void* const* d_in, const int* in_sizes, int n_in,
                              void* d_out, int out_size) {
    const float* x = (const float*)d_in[0];
    const float* y = (const float*)d_in[1];
    qk_fused<<<NBLK, 1024>>>(x, y, (float4*)d_out);
}

// round 7
// speedup vs baseline: 1.0072x; 1.0072x over previous
#include <cuda_runtime.h>
#include <math.h>

#define NW 22

// R7: hybrid store paths. 128 blocks x 1024 threads, 8 tiles (1024 float4) per
// block. Even tiles -> direct STG.128; odd tiles -> SMEM staging + TMA bulk
// store. Both drain paths run concurrently to test whether the ~2.4 TB/s store
// wall is per-path or global.
//
// Math (validated R2-R6):
//   out[4b+2i+j] = |TA[(b>>9)&1023]| * |TB[b&1023]| * S[c19,c0,c1,i,j]
//   b = (blk<<13)+(kk<<10)+t : TB idx = t, S idx from bits 0,18,19 (both
//   tile-invariant); TA idx warp-uniform.

__device__ __forceinline__ unsigned smem_u32(const void* p) {
    return (unsigned)__cvta_generic_to_shared(p);
}

__global__ void __launch_bounds__(1024) qk_fused(const float* __restrict__ x,
                                                 const float* __restrict__ y,
                                                 float4* __restrict__ out) {
    __shared__ float cx[NW], sx[NW], cy[NW], sy[NW];
    __shared__ float pc[NW], ps[NW];
    __shared__ float sTA[1024], sTB[1024];
    __shared__ float4 sS[8];
    __shared__ __align__(16) float4 sBuf[2][1024];   // staging for TMA tiles
    const int t = threadIdx.x;

    if (t < NW) {
        float sxx, cxx, syy, cyy;
        __sincosf(0.5f * x[t], &sxx, &cxx);
        __sincosf(0.5f * y[t], &syy, &cyy);
        cx[t] = cxx; sx[t] = sxx; cy[t] = cyy; sy[t] = syy;
        pc[t] = cxx * cyy; ps[t] = sxx * syy;
    }
    __syncthreads();

    // One TA and one TB entry per thread.
    {
        int u = t ^ (t >> 1);
        float a = 1.0f, bb = 1.0f;
        #pragma unroll
        for (int j = 0; j < 9; ++j) {
            bool bit = (u >> j) & 1;
            a  *= bit ? ps[10 - j] : pc[10 - j];   // wires 2..10
            bb *= bit ? ps[19 - j] : pc[19 - j];   // wires 11..19
        }
        sTA[t] = a;
        sTB[t] = bb;
    }

    // S table: pre-contracted 2x2 matmul tail, stored as abs (all entries >= 0).
    if (t < 32) {
        int j   =  t        & 1;
        int i   = (t >> 1)  & 1;
        int c1  = (t >> 2)  & 1;
        int c0  = (t >> 3)  & 1;
        int c19 = (t >> 4)  & 1;
        float s = 0.0f;
        #pragma unroll
        for (int k = 0; k < 2; ++k) {
            float ty = ((c19 ^ i)     ? sy[20] : cy[20])
                     * ((i   ^ k)     ? sy[21] : cy[21])
                     * ((c0  ^ k)     ? sy[0]  : cy[0])
                     * ((c0 ^ c1 ^ k) ? sy[1]  : cy[1]);
            float tx = ((c19 ^ k)     ? sx[20] : cx[20])
                     * ((k   ^ j)     ? sx[21] : cx[21])
                     * ((c0  ^ j)     ? sx[0]  : cx[0])
                     * ((c0 ^ c1 ^ j) ? sx[1]  : cx[1]);
            s += ty * tx;
        }
        reinterpret_cast<float*>(sS)[t] = fabsf(s);
    }
    __syncthreads();

    const unsigned base = (unsigned)blockIdx.x << 13;
    const unsigned b0 = base + (unsigned)t;
    const float4 s = sS[((b0 & 1u) << 2) | (((b0 >> 19) & 1u) << 1)
                        | ((b0 >> 18) & 1u)];
    const float Babs = fabsf(sTB[t]);
    const float Bsx = Babs * s.x, Bsy = Babs * s.y;
    const float Bsz = Babs * s.z, Bsw = Babs * s.w;

    #pragma unroll
    for (int kk = 0; kk < 8; ++kk) {
        unsigned b = b0 + ((unsigned)kk << 10);
        float A = fabsf(sTA[(b >> 9) & 1023u]);     // warp-uniform LDS
        float4 o;
        o.x = A * Bsx; o.y = A * Bsy; o.z = A * Bsz; o.w = A * Bsw;

        if ((kk & 1) == 0) {
            out[b] = o;                              // STG.128 path
        } else {
            const int buf = (kk >> 1) & 1;
            if (kk >= 5 && t == 0) {
                // Ensure the bulk group 2 tiles ago finished reading sBuf[buf].
                asm volatile("cp.async.bulk.wait_group.read 1;" ::: "memory");
            }
            __syncthreads();
            sBuf[buf][t] = o;                        // STS.128
            __syncthreads();
            if (t == 0) {
                asm volatile("fence.proxy.async.shared::cta;" ::: "memory");
                unsigned long long dst =
                    (unsigned long long)(out + base + ((unsigned)kk << 10));
                unsigned src = smem_u32(&sBuf[buf][0]);
                asm volatile(
                    "cp.async.bulk.global.shared::cta.bulk_group [%0], [%1], %2;"
                    :: "l"(dst), "r"(src), "n"(16384) : "memory");
                asm volatile("cp.async.bulk.commit_group;" ::: "memory");
            }
        }
    }

    // Drain outstanding bulk stores before block exit.
    if (t == 0) {
        asm volatile("cp.async.bulk.wait_group 0;" ::: "memory");
    }
    __syncthreads();
}

extern "C" void kernel_launch(void* const* d_in, const int* in_sizes, int n_in,
                              void* d_out, int out_size) {
    const float* x = (const float*)d_in[0];
    const float* y = (const float*)d_in[1];
    qk_fused<<<128, 1024>>>(x, y, (float4*)d_out);
}